// round 5
// baseline (speedup 1.0000x reference)
#include <cuda_runtime.h>

#define EPS    1e-5f
#define V_DIM  32
#define D_DIM  128
#define ITERS  32          // rows per warp

// ---------------------------------------------------------------------------
// 256-thread CTA = 8 warps. Global warp gw owns variable v = gw & 31 and row
// chunk group = gw >> 5. Lanes hold W/b/gamma/beta[v, lane*4..+3] in registers;
// warp computes per-v stats once via shuffles (analytic LayerNorm):
//   h  = x*W + b
//   mu = x*Wbar + bbar
//   var= x^2*Var(W) + 2x*Cov(W,b) + Var(b)
// Streaming (evict-first) loads for x and stores for out keep the write-once
// 512MB stream from churning L2 (the R4 win). Small CTAs -> 5 CTAs/SM at
// 48 regs for more store MLP / latency hiding than the 1-CTA/SM R4 config.
// ---------------------------------------------------------------------------
__global__ void __launch_bounds__(256)
ve_kernel(const float* __restrict__ x,
          const float* __restrict__ W,
          const float* __restrict__ b,
          const float* __restrict__ gamma,
          const float* __restrict__ beta,
          float* __restrict__ out) {
    int gw   = (blockIdx.x * blockDim.x + threadIdx.x) >> 5;
    int lane = threadIdx.x & 31;
    int v    = gw & (V_DIM - 1);
    int group = gw >> 5;             // row chunk for this v

    int t = v * 32 + lane;           // [V, D/4] table index
    float4 w4 = __ldg(reinterpret_cast<const float4*>(W)     + t);
    float4 b4 = __ldg(reinterpret_cast<const float4*>(b)     + t);
    float4 g4 = __ldg(reinterpret_cast<const float4*>(gamma) + t);
    float4 e4 = __ldg(reinterpret_cast<const float4*>(beta)  + t);

    // ---- per-v stats via butterfly reductions ----
    float sw = w4.x + w4.y + w4.z + w4.w;
    float sb = b4.x + b4.y + b4.z + b4.w;
    #pragma unroll
    for (int off = 16; off > 0; off >>= 1) {
        sw += __shfl_xor_sync(0xFFFFFFFFu, sw, off);
        sb += __shfl_xor_sync(0xFFFFFFFFu, sb, off);
    }
    float Wbar = sw * (1.0f / D_DIM);
    float bbar = sb * (1.0f / D_DIM);

    float wc0 = w4.x - Wbar, wc1 = w4.y - Wbar, wc2 = w4.z - Wbar, wc3 = w4.w - Wbar;
    float bc0 = b4.x - bbar, bc1 = b4.y - bbar, bc2 = b4.z - bbar, bc3 = b4.w - bbar;
    float sww = wc0*wc0 + wc1*wc1 + wc2*wc2 + wc3*wc3;
    float swb = wc0*bc0 + wc1*bc1 + wc2*bc2 + wc3*bc3;
    float sbb = bc0*bc0 + bc1*bc1 + bc2*bc2 + bc3*bc3;
    #pragma unroll
    for (int off = 16; off > 0; off >>= 1) {
        sww += __shfl_xor_sync(0xFFFFFFFFu, sww, off);
        swb += __shfl_xor_sync(0xFFFFFFFFu, swb, off);
        sbb += __shfl_xor_sync(0xFFFFFFFFu, sbb, off);
    }
    float varW = sww * (1.0f / D_DIM);
    float cov2 = swb * (2.0f / D_DIM);   // 2*Cov(W,b)
    float varb = sbb * (1.0f / D_DIM);

    int n0 = group * ITERS;
    const float* xp = x + (size_t)n0 * V_DIM + v;               // x[n*V + v]
    float4* orow = reinterpret_cast<float4*>(out)
                 + ((size_t)n0 * V_DIM + v) * 32 + lane;        // out row base

    #pragma unroll 4
    for (int i = 0; i < ITERS; i++) {
        float xv  = __ldcs(xp + (size_t)i * V_DIM);             // read-once stream

        float var = fmaf(xv, fmaf(xv, varW, cov2), varb);
        float rs  = rsqrtf(var + EPS);
        float mu  = fmaf(xv, Wbar, bbar);
        float nmr = -mu * rs;            // (h-mu)*rs == fma(h, rs, nmr)

        float4 o;
        { float h = fmaf(w4.x, xv, b4.x); float y = fmaf(h, rs, nmr);
          o.x = fmaxf(fmaf(g4.x, y, e4.x), 0.0f); }
        { float h = fmaf(w4.y, xv, b4.y); float y = fmaf(h, rs, nmr);
          o.y = fmaxf(fmaf(g4.y, y, e4.y), 0.0f); }
        { float h = fmaf(w4.z, xv, b4.z); float y = fmaf(h, rs, nmr);
          o.z = fmaxf(fmaf(g4.z, y, e4.z), 0.0f); }
        { float h = fmaf(w4.w, xv, b4.w); float y = fmaf(h, rs, nmr);
          o.w = fmaxf(fmaf(g4.w, y, e4.w), 0.0f); }

        // evict-first streaming store: output is write-once, never re-read
        __stcs(orow + (size_t)i * (V_DIM * 32), o);
    }
}

// ---------------------------------------------------------------------------
extern "C" void kernel_launch(void* const* d_in, const int* in_sizes, int n_in,
                              void* d_out, int out_size) {
    const float* x     = (const float*)d_in[0];
    const float* W     = (const float*)d_in[1];
    const float* b     = (const float*)d_in[2];
    const float* gamma = (const float*)d_in[3];
    const float* beta  = (const float*)d_in[4];
    float* out = (float*)d_out;

    // rows = out_size / D = 1,048,576 ; per_v = rows / V = 32,768
    // warps = V * per_v / ITERS = 32,768 ; 8 warps per 256-thread CTA
    long long rows  = (long long)out_size / D_DIM;
    long long per_v = rows / V_DIM;
    long long warps = (per_v / ITERS) * V_DIM;
    int threads = 256;
    int blocks  = (int)(warps * 32 / threads);   // 4096

    ve_kernel<<<blocks, threads>>>(x, W, b, gamma, beta, out);
}

// round 6
// speedup vs baseline: 1.4689x; 1.4689x over previous
#include <cuda_runtime.h>

#define EPS    1e-5f
#define V_DIM  32
#define D_DIM  128
#define NPER   32          // n-units (16KB each) per CTA, processed in pairs

// ---------------------------------------------------------------------------
// 1024-thread CTA = 32 warps; warp w owns variable v = w (R4 structure: each
// CTA iteration writes a CONTIGUOUS block of output — this density is what
// makes evict-first stores win; scattered evict-first regressed in R5).
// Lanes hold W/b/gamma/beta[v, lane*4..+3] in registers; warp computes per-v
// stats once via shuffles (analytic LayerNorm — no per-row reduction):
//   h  = x*W + b
//   mu = x*Wbar + bbar
//   var= x^2*Var(W) + 2x*Cov(W,b) + Var(b)
// New vs R4: 2 n-units per loop iteration (32KB contiguous per CTA-iter) for
// 2x store MLP per warp and half the loop overhead.
// ---------------------------------------------------------------------------
__global__ void __launch_bounds__(1024, 1)
ve_kernel(const float* __restrict__ x,
          const float* __restrict__ W,
          const float* __restrict__ b,
          const float* __restrict__ gamma,
          const float* __restrict__ beta,
          float* __restrict__ out) {
    int v    = threadIdx.x >> 5;     // warp id = variable index
    int lane = threadIdx.x & 31;

    int t = v * 32 + lane;           // [V, D/4] table index
    float4 w4 = __ldg(reinterpret_cast<const float4*>(W)     + t);
    float4 b4 = __ldg(reinterpret_cast<const float4*>(b)     + t);
    float4 g4 = __ldg(reinterpret_cast<const float4*>(gamma) + t);
    float4 e4 = __ldg(reinterpret_cast<const float4*>(beta)  + t);

    // ---- per-v stats via butterfly reductions ----
    float sw = w4.x + w4.y + w4.z + w4.w;
    float sb = b4.x + b4.y + b4.z + b4.w;
    #pragma unroll
    for (int off = 16; off > 0; off >>= 1) {
        sw += __shfl_xor_sync(0xFFFFFFFFu, sw, off);
        sb += __shfl_xor_sync(0xFFFFFFFFu, sb, off);
    }
    float Wbar = sw * (1.0f / D_DIM);
    float bbar = sb * (1.0f / D_DIM);

    float wc0 = w4.x - Wbar, wc1 = w4.y - Wbar, wc2 = w4.z - Wbar, wc3 = w4.w - Wbar;
    float bc0 = b4.x - bbar, bc1 = b4.y - bbar, bc2 = b4.z - bbar, bc3 = b4.w - bbar;
    float sww = wc0*wc0 + wc1*wc1 + wc2*wc2 + wc3*wc3;
    float swb = wc0*bc0 + wc1*bc1 + wc2*bc2 + wc3*bc3;
    float sbb = bc0*bc0 + bc1*bc1 + bc2*bc2 + bc3*bc3;
    #pragma unroll
    for (int off = 16; off > 0; off >>= 1) {
        sww += __shfl_xor_sync(0xFFFFFFFFu, sww, off);
        swb += __shfl_xor_sync(0xFFFFFFFFu, swb, off);
        sbb += __shfl_xor_sync(0xFFFFFFFFu, sbb, off);
    }
    float varW = sww * (1.0f / D_DIM);
    float cov2 = swb * (2.0f / D_DIM);   // 2*Cov(W,b)
    float varb = sbb * (1.0f / D_DIM);

    int n0 = blockIdx.x * NPER;
    const float* xp = x + (size_t)n0 * V_DIM + v;               // x[n*V + v]
    float4* orow = reinterpret_cast<float4*>(out)
                 + ((size_t)n0 * V_DIM + v) * 32 + lane;        // row base
    const int UNIT4 = V_DIM * 32;                                // float4s per n-unit

    #pragma unroll 4
    for (int i = 0; i < NPER / 2; i++) {
        float xv0 = __ldg(xp + (size_t)(2 * i)     * V_DIM);
        float xv1 = __ldg(xp + (size_t)(2 * i + 1) * V_DIM);

        // ---- row 0 ----
        float var0 = fmaf(xv0, fmaf(xv0, varW, cov2), varb);
        float rs0  = rsqrtf(var0 + EPS);
        float nm0  = -fmaf(xv0, Wbar, bbar) * rs0;
        // ---- row 1 ----
        float var1 = fmaf(xv1, fmaf(xv1, varW, cov2), varb);
        float rs1  = rsqrtf(var1 + EPS);
        float nm1  = -fmaf(xv1, Wbar, bbar) * rs1;

        float4 o0, o1;
        { float h = fmaf(w4.x, xv0, b4.x); float y = fmaf(h, rs0, nm0);
          o0.x = fmaxf(fmaf(g4.x, y, e4.x), 0.0f); }
        { float h = fmaf(w4.y, xv0, b4.y); float y = fmaf(h, rs0, nm0);
          o0.y = fmaxf(fmaf(g4.y, y, e4.y), 0.0f); }
        { float h = fmaf(w4.z, xv0, b4.z); float y = fmaf(h, rs0, nm0);
          o0.z = fmaxf(fmaf(g4.z, y, e4.z), 0.0f); }
        { float h = fmaf(w4.w, xv0, b4.w); float y = fmaf(h, rs0, nm0);
          o0.w = fmaxf(fmaf(g4.w, y, e4.w), 0.0f); }

        { float h = fmaf(w4.x, xv1, b4.x); float y = fmaf(h, rs1, nm1);
          o1.x = fmaxf(fmaf(g4.x, y, e4.x), 0.0f); }
        { float h = fmaf(w4.y, xv1, b4.y); float y = fmaf(h, rs1, nm1);
          o1.y = fmaxf(fmaf(g4.y, y, e4.y), 0.0f); }
        { float h = fmaf(w4.z, xv1, b4.z); float y = fmaf(h, rs1, nm1);
          o1.z = fmaxf(fmaf(g4.z, y, e4.z), 0.0f); }
        { float h = fmaf(w4.w, xv1, b4.w); float y = fmaf(h, rs1, nm1);
          o1.w = fmaxf(fmaf(g4.w, y, e4.w), 0.0f); }

        // evict-first streaming stores: write-once output, dense CTA footprint
        __stcs(orow + (size_t)(2 * i)     * UNIT4, o0);
        __stcs(orow + (size_t)(2 * i + 1) * UNIT4, o1);
    }
}

// ---------------------------------------------------------------------------
extern "C" void kernel_launch(void* const* d_in, const int* in_sizes, int n_in,
                              void* d_out, int out_size) {
    const float* x     = (const float*)d_in[0];
    const float* W     = (const float*)d_in[1];
    const float* b     = (const float*)d_in[2];
    const float* gamma = (const float*)d_in[3];
    const float* beta  = (const float*)d_in[4];
    float* out = (float*)d_out;

    // n-units of 16KB = out_size / (V*D) = 32768 ; blocks = 32768/NPER = 1024
    int n_units = out_size / (V_DIM * D_DIM);
    int blocks  = n_units / NPER;

    ve_kernel<<<blocks, 1024>>>(x, W, b, gamma, beta, out);
}

// round 7
// speedup vs baseline: 1.4746x; 1.0039x over previous
#include <cuda_runtime.h>

#define EPS    1e-5f
#define V_DIM  32
#define D_DIM  128
#define NPER   32          // n-units (16KB each) per CTA, processed 4 at a time

// ---------------------------------------------------------------------------
// 1024-thread CTA = 32 warps; warp w owns variable v = w. Each CTA iteration
// writes a CONTIGUOUS 64KB block (4 n-units) — dense CTA write footprint is
// what makes evict-first stores win (R4/R6 vs R5 evidence).
// Lanes hold W/b/gamma/beta[v, lane*4..+3] in registers; warp computes per-v
// stats once via shuffles (analytic LayerNorm — no per-row reduction):
//   h  = x*W + b ;  mu = x*Wbar + bbar ;  var = x^2 VarW + 2x Cov + Varb
// R7 change vs R6: 4 rows per loop iteration with front-batched x loads for
// deeper store/load MLP per warp at the same occupancy.
// ---------------------------------------------------------------------------
__global__ void __launch_bounds__(1024, 1)
ve_kernel(const float* __restrict__ x,
          const float* __restrict__ W,
          const float* __restrict__ b,
          const float* __restrict__ gamma,
          const float* __restrict__ beta,
          float* __restrict__ out) {
    int v    = threadIdx.x >> 5;     // warp id = variable index
    int lane = threadIdx.x & 31;

    int t = v * 32 + lane;           // [V, D/4] table index
    float4 w4 = __ldg(reinterpret_cast<const float4*>(W)     + t);
    float4 b4 = __ldg(reinterpret_cast<const float4*>(b)     + t);
    float4 g4 = __ldg(reinterpret_cast<const float4*>(gamma) + t);
    float4 e4 = __ldg(reinterpret_cast<const float4*>(beta)  + t);

    // ---- per-v stats via butterfly reductions ----
    float sw = w4.x + w4.y + w4.z + w4.w;
    float sb = b4.x + b4.y + b4.z + b4.w;
    #pragma unroll
    for (int off = 16; off > 0; off >>= 1) {
        sw += __shfl_xor_sync(0xFFFFFFFFu, sw, off);
        sb += __shfl_xor_sync(0xFFFFFFFFu, sb, off);
    }
    float Wbar = sw * (1.0f / D_DIM);
    float bbar = sb * (1.0f / D_DIM);

    float wc0 = w4.x - Wbar, wc1 = w4.y - Wbar, wc2 = w4.z - Wbar, wc3 = w4.w - Wbar;
    float bc0 = b4.x - bbar, bc1 = b4.y - bbar, bc2 = b4.z - bbar, bc3 = b4.w - bbar;
    float sww = wc0*wc0 + wc1*wc1 + wc2*wc2 + wc3*wc3;
    float swb = wc0*bc0 + wc1*bc1 + wc2*bc2 + wc3*bc3;
    float sbb = bc0*bc0 + bc1*bc1 + bc2*bc2 + bc3*bc3;
    #pragma unroll
    for (int off = 16; off > 0; off >>= 1) {
        sww += __shfl_xor_sync(0xFFFFFFFFu, sww, off);
        swb += __shfl_xor_sync(0xFFFFFFFFu, swb, off);
        sbb += __shfl_xor_sync(0xFFFFFFFFu, sbb, off);
    }
    float varW = sww * (1.0f / D_DIM);
    float cov2 = swb * (2.0f / D_DIM);   // 2*Cov(W,b)
    float varb = sbb * (1.0f / D_DIM);

    int n0 = blockIdx.x * NPER;
    const float* xp = x + (size_t)n0 * V_DIM + v;               // x[n*V + v]
    float4* orow = reinterpret_cast<float4*>(out)
                 + ((size_t)n0 * V_DIM + v) * 32 + lane;        // row base
    const int UNIT4 = V_DIM * 32;                                // float4s per n-unit

    #pragma unroll 2
    for (int i = 0; i < NPER / 4; i++) {
        // front-batch 4 independent x loads
        float xv0 = __ldg(xp + (size_t)(4 * i)     * V_DIM);
        float xv1 = __ldg(xp + (size_t)(4 * i + 1) * V_DIM);
        float xv2 = __ldg(xp + (size_t)(4 * i + 2) * V_DIM);
        float xv3 = __ldg(xp + (size_t)(4 * i + 3) * V_DIM);

        float rs0 = rsqrtf(fmaf(xv0, fmaf(xv0, varW, cov2), varb) + EPS);
        float rs1 = rsqrtf(fmaf(xv1, fmaf(xv1, varW, cov2), varb) + EPS);
        float rs2 = rsqrtf(fmaf(xv2, fmaf(xv2, varW, cov2), varb) + EPS);
        float rs3 = rsqrtf(fmaf(xv3, fmaf(xv3, varW, cov2), varb) + EPS);
        float nm0 = -fmaf(xv0, Wbar, bbar) * rs0;
        float nm1 = -fmaf(xv1, Wbar, bbar) * rs1;
        float nm2 = -fmaf(xv2, Wbar, bbar) * rs2;
        float nm3 = -fmaf(xv3, Wbar, bbar) * rs3;

        #define ROW_OUT(o, xv, rs, nm)                                        \
        {                                                                     \
            { float h = fmaf(w4.x, xv, b4.x); float y = fmaf(h, rs, nm);      \
              o.x = fmaxf(fmaf(g4.x, y, e4.x), 0.0f); }                       \
            { float h = fmaf(w4.y, xv, b4.y); float y = fmaf(h, rs, nm);      \
              o.y = fmaxf(fmaf(g4.y, y, e4.y), 0.0f); }                       \
            { float h = fmaf(w4.z, xv, b4.z); float y = fmaf(h, rs, nm);      \
              o.z = fmaxf(fmaf(g4.z, y, e4.z), 0.0f); }                       \
            { float h = fmaf(w4.w, xv, b4.w); float y = fmaf(h, rs, nm);      \
              o.w = fmaxf(fmaf(g4.w, y, e4.w), 0.0f); }                       \
        }

        float4 o0; ROW_OUT(o0, xv0, rs0, nm0);
        float4 o1; ROW_OUT(o1, xv1, rs1, nm1);
        __stcs(orow + (size_t)(4 * i)     * UNIT4, o0);
        __stcs(orow + (size_t)(4 * i + 1) * UNIT4, o1);
        float4 o2; ROW_OUT(o2, xv2, rs2, nm2);
        float4 o3; ROW_OUT(o3, xv3, rs3, nm3);
        __stcs(orow + (size_t)(4 * i + 2) * UNIT4, o2);
        __stcs(orow + (size_t)(4 * i + 3) * UNIT4, o3);

        #undef ROW_OUT
    }
}

// ---------------------------------------------------------------------------
extern "C" void kernel_launch(void* const* d_in, const int* in_sizes, int n_in,
                              void* d_out, int out_size) {
    const float* x     = (const float*)d_in[0];
    const float* W     = (const float*)d_in[1];
    const float* b     = (const float*)d_in[2];
    const float* gamma = (const float*)d_in[3];
    const float* beta  = (const float*)d_in[4];
    float* out = (float*)d_out;

    // n-units of 16KB = out_size / (V*D) = 32768 ; blocks = 32768/NPER = 1024
    int n_units = out_size / (V_DIM * D_DIM);
    int blocks  = n_units / NPER;

    ve_kernel<<<blocks, 1024>>>(x, W, b, gamma, beta, out);
}